// round 12
// baseline (speedup 1.0000x reference)
#include <cuda_runtime.h>
#include <math.h>

#define SW    192
#define SHW   (192*192)
#define HPX   188
#define NC    32
#define NB    2
#define EPS_F 1e-8f
#define GX    12
#define GY    47
#define NBLK  (GX*GY*NB)   // 1128

__device__ double       g_part[NBLK];
__device__ unsigned int g_ctr = 0;

typedef unsigned long long u64;

// ---- packed f32x2 helpers (Blackwell FFMA2 path) ----
__device__ __forceinline__ u64 pack2(float lo, float hi) {
    u64 r; asm("mov.b64 %0, {%1, %2};" : "=l"(r) : "f"(lo), "f"(hi)); return r;
}
__device__ __forceinline__ void unpack2(u64 v, float& lo, float& hi) {
    asm("mov.b64 {%0, %1}, %2;" : "=f"(lo), "=f"(hi) : "l"(v));
}
__device__ __forceinline__ u64 add2(u64 a, u64 b) {
    u64 r; asm("add.rn.f32x2 %0, %1, %2;" : "=l"(r) : "l"(a), "l"(b)); return r;
}
__device__ __forceinline__ u64 fma2(u64 a, u64 b, u64 c) {
    u64 r; asm("fma.rn.f32x2 %0, %1, %2, %3;" : "=l"(r) : "l"(a), "l"(b), "l"(c)); return r;
}

// Replicates XLA EmitExpm1 then "+1.0" (validated rel_err 0.0 in R7-R9):
//   em1 = |x| < 1e-5 ? x + (x*x)*0.5 : exp(x) - 1 ; return em1 + 1
__device__ __forceinline__ float xla_expm1_p1(float x) {
    float em1;
    if (fabsf(x) < 1e-5f) {
        em1 = __fadd_rn(x, __fmul_rn(__fmul_rn(x, x), 0.5f));
    } else {
        float e = (float)exp((double)x);
        em1 = __fsub_rn(e, 1.0f);
    }
    return __fadd_rn(em1, 1.0f);
}

__global__ __launch_bounds__(128)
void dgp_kernel(const float* __restrict__ sem, const float* __restrict__ depth,
                float* __restrict__ out) {
    const int lane = threadIdx.x;                  // block (32, 4)
    const int xp   = lane & 7;                     // x-pair within warp segment
    const int cq   = lane >> 3;                    // channel quarter (8 ch each)
    const int pair = blockIdx.x * 8 + xp;          // global x-pair index (0..95)
    const int x0   = 2 * pair;                     // even window start (= xc0 - 2)
    const int r0   = blockIdx.y * 4 + threadIdx.y; // 47*4 = 188 exact
    const int b    = blockIdx.z;
    const bool valid = (x0 < HPX);                 // pair < 94
    const int y = r0 + 2;

    // acc[di][dj]: packed partial squared distances (this quarter's 8 channels)
    u64 acc[5][5];
    #pragma unroll
    for (int i = 0; i < 5; i++)
        #pragma unroll
        for (int j = 0; j < 5; j++)
            acc[i][j] = 0ull;

    if (valid) {
        const float* __restrict__ base =
            sem + ((size_t)(b * NC + cq * 8)) * SHW + y * SW + x0;

        #pragma unroll
        for (int ch = 0; ch < 8; ch++) {
            const float* __restrict__ pc = base + ch * SHW;

            // ---- center row (di=2): also yields the negated center pair ----
            float2 c0 = *(const float2*)(pc);
            float2 c1 = *(const float2*)(pc + 2);
            float2 c2 = *(const float2*)(pc + 4);
            const u64 nctr = pack2(-c1.x, -c1.y);          // -(w2, w3)
            {
                u64 d;
                d = add2(pack2(c0.x, c0.y), nctr); acc[2][0] = fma2(d, d, acc[2][0]);
                d = add2(pack2(c0.y, c1.x), nctr); acc[2][1] = fma2(d, d, acc[2][1]);
                /* dj=2 masked center: identically 0 */
                d = add2(pack2(c1.y, c2.x), nctr); acc[2][3] = fma2(d, d, acc[2][3]);
                d = add2(pack2(c2.x, c2.y), nctr); acc[2][4] = fma2(d, d, acc[2][4]);
            }
            // ---- other 4 rows ----
            #pragma unroll
            for (int di = 0; di < 5; di++) {
                if (di == 2) continue;
                const float* __restrict__ pr = pc + (di - 2) * SW;
                float2 a0 = *(const float2*)(pr);
                float2 a1 = *(const float2*)(pr + 2);
                float2 a2 = *(const float2*)(pr + 4);
                u64 d;
                d = add2(pack2(a0.x, a0.y), nctr); acc[di][0] = fma2(d, d, acc[di][0]);
                d = add2(pack2(a0.y, a1.x), nctr); acc[di][1] = fma2(d, d, acc[di][1]);
                d = add2(pack2(a1.x, a1.y), nctr); acc[di][2] = fma2(d, d, acc[di][2]);
                d = add2(pack2(a1.y, a2.x), nctr); acc[di][3] = fma2(d, d, acc[di][3]);
                d = add2(pack2(a2.x, a2.y), nctr); acc[di][4] = fma2(d, d, acc[di][4]);
            }
        }
    }

    // ---- butterfly combine across the 4 channel quarters (uniform: all lanes) ----
    #pragma unroll
    for (int di = 0; di < 5; di++)
        #pragma unroll
        for (int dj = 0; dj < 5; dj++) {
            if (di == 2 && dj == 2) continue;
            u64 v = acc[di][dj];
            v = add2(v, __shfl_xor_sync(0xffffffffu, v, 8));
            v = add2(v, __shfl_xor_sync(0xffffffffu, v, 16));
            acc[di][dj] = v;
        }

    double dsum = 0.0;
    // gate: quarter-0 lanes only (others hold duplicate sums)
    if (valid && cq == 0) {
        #pragma unroll
        for (int di = 0; di < 5; di++)
            #pragma unroll
            for (int dj = 0; dj < 5; dj++) {
                if (di == 2 && dj == 2) continue;
                float s0, s1;
                unpack2(acc[di][dj], s0, s1);
                #pragma unroll
                for (int p = 0; p < 2; p++) {
                    float sg = p ? s1 : s0;
                    // margin 18.5 > exact cutoff 18.02; absorbs contraction/tree-order drift
                    if (sg < 18.5f) {
                        // rare exact XLA-order recompute for this (pos, offset)
                        const int xc  = x0 + 2 + p;
                        const int off = (di - 2) * SW + (dj - 2);
                        const float* __restrict__ sp =
                            sem + ((size_t)b * NC) * SHW + y * SW + xc;
                        float s = 0.0f;
                        for (int ch = 0; ch < NC; ch++) {
                            float d = __fsub_rn(sp[ch * SHW + off], sp[ch * SHW]);
                            s = __fadd_rn(s, __fmul_rn(d, d));
                        }
                        float sd  = fmaxf(__fsqrt_rn(s), EPS_F);
                        float ssq = __fmul_rn(sd, sd);
                        const float* __restrict__ dpp = depth + b * SHW + y * SW + xc;
                        float invc = __fdiv_rn(1.0f, __fadd_rn(dpp[0],   1e-6f));
                        float invo = __fdiv_rn(1.0f, __fadd_rn(dpp[off], 1e-6f));
                        float dd   = fmaxf(fabsf(__fsub_rn(invc, invo)), EPS_F);
                        if (dd > EPS_F && sd > EPS_F) {
                            float f1 = xla_expm1_p1(-__fdiv_rn(dd, 10.0f));
                            float f2 = xla_expm1_p1(-ssq);
                            dsum += (double)__fmul_rn(f1, f2);
                        }
                    }
                }
            }
    }

    // ---- block reduction -> per-block slot ----
    const int tid = threadIdx.y * 32 + threadIdx.x;
    const int wid = tid >> 5, lne = tid & 31;
    #pragma unroll
    for (int o = 16; o > 0; o >>= 1)
        dsum += __shfl_down_sync(0xffffffffu, dsum, o);

    __shared__ double ws[4];
    __shared__ bool   is_last;
    if (lne == 0) ws[wid] = dsum;
    __syncthreads();

    const int bid = (blockIdx.z * GY + blockIdx.y) * GX + blockIdx.x;
    if (tid == 0) {
        g_part[bid] = ws[0] + ws[1] + ws[2] + ws[3];
        __threadfence();
        unsigned old = atomicAdd(&g_ctr, 1u);
        is_last = (old == NBLK - 1);
    }
    __syncthreads();

    // ---- last block finalizes (single launch total) ----
    if (is_last) {
        double v = 0.0;
        for (int i = tid; i < NBLK; i += 128) v += g_part[i];
        #pragma unroll
        for (int o = 16; o > 0; o >>= 1)
            v += __shfl_down_sync(0xffffffffu, v, o);
        __shared__ double fs[4];
        if (lne == 0) fs[wid] = v;
        __syncthreads();
        if (tid == 0) {
            double s = fs[0] + fs[1] + fs[2] + fs[3];
            // mean over (B,B,k,k,P): S / (25*B*P) = S / 1,767,200
            out[0] = (float)(s / 1767200.0);
            g_ctr  = 0;          // reset for next graph replay
        }
    }
}

extern "C" void kernel_launch(void* const* d_in, const int* in_sizes, int n_in,
                              void* d_out, int out_size) {
    const float* sem   = (const float*)d_in[0];  // (2, 32, 192, 192) f32
    const float* depth = (const float*)d_in[1];  // (2, 1, 192, 192) f32

    dim3 blk(32, 4);
    dim3 grd(GX, GY, NB);
    dgp_kernel<<<grd, blk>>>(sem, depth, (float*)d_out);
}

// round 13
// speedup vs baseline: 1.4304x; 1.4304x over previous
#include <cuda_runtime.h>
#include <math.h>

#define SW    192
#define SHW   (192*192)
#define HPX   188
#define NC    32
#define NB    2
#define EPS_F 1e-8f
#define GXB   6
#define GYB   24
#define NBLK  (GXB*GYB*NB)   // 288
#define SLABW 36             // 32 + 4 halo
#define SLABH 12             // 8 + 4 halo
#define SLABN (SLABW*SLABH)  // 432

__device__ double       g_part[NBLK];
__device__ unsigned int g_ctr = 0;

// Replicates XLA EmitExpm1 then "+1.0" (validated rel_err 0.0 in R7-R12):
//   em1 = |x| < 1e-5 ? x + (x*x)*0.5 : exp(x) - 1 ; return em1 + 1
__device__ __forceinline__ float xla_expm1_p1(float x) {
    float em1;
    if (fabsf(x) < 1e-5f) {
        em1 = __fadd_rn(x, __fmul_rn(__fmul_rn(x, x), 0.5f));
    } else {
        float e = (float)exp((double)x);
        em1 = __fsub_rn(e, 1.0f);
    }
    return __fadd_rn(em1, 1.0f);
}

__global__ __launch_bounds__(256)
void dgp_kernel(const float* __restrict__ sem, const float* __restrict__ depth,
                float* __restrict__ out) {
    __shared__ float sbuf[2][SLABN];

    const int tx = threadIdx.x, ty = threadIdx.y;    // block (32, 8)
    const int tid = ty * 32 + tx;
    const int bx = blockIdx.x, by = blockIdx.y, b = blockIdx.z;

    const int px = bx * 32 + tx;                     // output position
    const int py = by * 8 + ty;
    const bool valid = (px < HPX) && (py < HPX);

    // slab load coordinates (computed once; clamped values only feed invalid positions)
    const int i0 = tid, i1 = tid + 256;
    const int r0 = i0 / SLABW, c0 = i0 % SLABW;
    const int g0 = min(by * 8 + r0, SW - 1) * SW + min(bx * 32 + c0, SW - 1);
    int g1 = 0;
    if (i1 < SLABN) {
        const int r1 = i1 / SLABW, c1 = i1 % SLABW;
        g1 = min(by * 8 + r1, SW - 1) * SW + min(bx * 32 + c1, SW - 1);
    }

    const float* __restrict__ chbase = sem + ((size_t)b * NC) * SHW;

    float acc[5][5];
    #pragma unroll
    for (int i = 0; i < 5; i++)
        #pragma unroll
        for (int j = 0; j < 5; j++)
            acc[i][j] = 0.0f;

    // preload channel 0
    float v0 = chbase[g0];
    float v1 = (i1 < SLABN) ? chbase[g1] : 0.0f;

    #pragma unroll 1
    for (int ch = 0; ch < NC; ch++) {
        float* sb = sbuf[ch & 1];
        sb[i0] = v0;
        if (i1 < SLABN) sb[i1] = v1;
        __syncthreads();

        // prefetch next channel while computing this one
        if (ch + 1 < NC) {
            const float* __restrict__ nb = chbase + (ch + 1) * SHW;
            v0 = nb[g0];
            if (i1 < SLABN) v1 = nb[g1];
        }

        const float c = sb[(ty + 2) * SLABW + tx + 2];
        #pragma unroll
        for (int di = 0; di < 5; di++) {
            const float* row = sb + (ty + di) * SLABW + tx;
            #pragma unroll
            for (int dj = 0; dj < 5; dj++) {
                if (di == 2 && dj == 2) continue;    // center mask
                float d = row[dj] - c;
                acc[di][dj] = fmaf(d, d, acc[di][dj]);
            }
        }
        // no trailing sync needed: next iter writes the OTHER buffer, whose last
        // readers (compute of ch-1) are provably past this iteration's barrier.
    }

    // ---- gate + rare exact path (validated) ----
    double dsum = 0.0;
    if (valid) {
        const int y = py + 2, xc = px + 2;
        #pragma unroll
        for (int di = 0; di < 5; di++)
            #pragma unroll
            for (int dj = 0; dj < 5; dj++) {
                if (di == 2 && dj == 2) continue;
                // margin 18.5 > exact cutoff 18.02; absorbs fma-contraction drift
                if (acc[di][dj] < 18.5f) {
                    const int off = (di - 2) * SW + (dj - 2);
                    const float* __restrict__ sp = chbase + y * SW + xc;
                    float s = 0.0f;
                    for (int ch = 0; ch < NC; ch++) {
                        float d = __fsub_rn(sp[ch * SHW + off], sp[ch * SHW]);
                        s = __fadd_rn(s, __fmul_rn(d, d));
                    }
                    float sd  = fmaxf(__fsqrt_rn(s), EPS_F);
                    float ssq = __fmul_rn(sd, sd);
                    const float* __restrict__ dpp = depth + b * SHW + y * SW + xc;
                    float invc = __fdiv_rn(1.0f, __fadd_rn(dpp[0],   1e-6f));
                    float invo = __fdiv_rn(1.0f, __fadd_rn(dpp[off], 1e-6f));
                    float dd   = fmaxf(fabsf(__fsub_rn(invc, invo)), EPS_F);
                    if (dd > EPS_F && sd > EPS_F) {
                        float f1 = xla_expm1_p1(-__fdiv_rn(dd, 10.0f));
                        float f2 = xla_expm1_p1(-ssq);
                        dsum += (double)__fmul_rn(f1, f2);
                    }
                }
            }
    }

    // ---- block reduction -> per-block slot ----
    const int wid = tid >> 5, lne = tid & 31;
    #pragma unroll
    for (int o = 16; o > 0; o >>= 1)
        dsum += __shfl_down_sync(0xffffffffu, dsum, o);

    __shared__ double ws[8];
    __shared__ bool   is_last;
    if (lne == 0) ws[wid] = dsum;
    __syncthreads();

    const int bid = (b * GYB + by) * GXB + bx;
    if (tid == 0) {
        double t = 0.0;
        #pragma unroll
        for (int w = 0; w < 8; w++) t += ws[w];
        g_part[bid] = t;
        __threadfence();
        unsigned old = atomicAdd(&g_ctr, 1u);
        is_last = (old == NBLK - 1);
    }
    __syncthreads();

    // ---- last block finalizes (single launch total) ----
    if (is_last) {
        double v = 0.0;
        for (int i = tid; i < NBLK; i += 256) v += g_part[i];
        #pragma unroll
        for (int o = 16; o > 0; o >>= 1)
            v += __shfl_down_sync(0xffffffffu, v, o);
        __shared__ double fs[8];
        if (lne == 0) fs[wid] = v;
        __syncthreads();
        if (tid == 0) {
            double s = 0.0;
            #pragma unroll
            for (int w = 0; w < 8; w++) s += fs[w];
            // mean over (B,B,k,k,P): S / (25*B*P) = S / 1,767,200
            out[0] = (float)(s / 1767200.0);
            g_ctr  = 0;          // reset for next graph replay
        }
    }
}

extern "C" void kernel_launch(void* const* d_in, const int* in_sizes, int n_in,
                              void* d_out, int out_size) {
    const float* sem   = (const float*)d_in[0];  // (2, 32, 192, 192) f32
    const float* depth = (const float*)d_in[1];  // (2, 1, 192, 192) f32

    dim3 blk(32, 8);
    dim3 grd(GXB, GYB, NB);
    dgp_kernel<<<grd, blk>>>(sem, depth, (float*)d_out);
}

// round 14
// speedup vs baseline: 1.7010x; 1.1892x over previous
#include <cuda_runtime.h>
#include <math.h>

#define SW    192
#define SHW   (192*192)
#define HPX   188
#define NC    32
#define NB    2
#define EPS_F 1e-8f
#define GXB   6
#define GYB   24
#define NBLK  (GXB*GYB*NB)   // 288

__device__ double       g_part[NBLK];
__device__ unsigned int g_ctr = 0;

// Replicates XLA EmitExpm1 then "+1.0" (validated rel_err 0.0 in R7-R13):
//   em1 = |x| < 1e-5 ? x + (x*x)*0.5 : exp(x) - 1 ; return em1 + 1
__device__ __forceinline__ float xla_expm1_p1(float x) {
    float em1;
    if (fabsf(x) < 1e-5f) {
        em1 = __fadd_rn(x, __fmul_rn(__fmul_rn(x, x), 0.5f));
    } else {
        float e = (float)exp((double)x);
        em1 = __fsub_rn(e, 1.0f);
    }
    return __fadd_rn(em1, 1.0f);
}

__global__ __launch_bounds__(256)
void dgp_kernel(const float* __restrict__ sem, const float* __restrict__ depth,
                float* __restrict__ out) {
    const int tx = threadIdx.x, ty = threadIdx.y;   // block (32, 8)
    const int tid = ty * 32 + tx;
    const int px = blockIdx.x * 32 + tx;            // output position
    const int py = blockIdx.y * 8 + ty;
    const int b  = blockIdx.z;
    const bool valid = (px < HPX) && (py < HPX);

    double dsum = 0.0;

    if (valid) {
        const int y = py + 2, x = px + 2;           // center pixel
        const float* __restrict__ sp = sem + ((size_t)b * NC) * SHW + y * SW + x;

        // cache center's 32 channels in registers (coalesced: warp spans 32 consecutive x)
        float center[NC];
        #pragma unroll
        for (int ch = 0; ch < NC; ch++) center[ch] = sp[ch * SHW];

        #pragma unroll
        for (int di = -2; di <= 2; di++) {
            #pragma unroll
            for (int dj = -2; dj <= 2; dj++) {
                if (di == 0 && dj == 0) continue;   // center_mask
                const int off = di * SW + dj;
                // hot path: contracted FMA (2 ops/ch), 32 independent loads in flight
                float s = 0.0f;
                #pragma unroll
                for (int ch = 0; ch < NC; ch++) {
                    float d = sp[ch * SHW + off] - center[ch];
                    s = fmaf(d, d, s);
                }
                // gate: margin 18.5 > exact cutoff 18.02 (expm1f(-x)+1 == 0 beyond);
                // absorbs fma-contraction drift. Rare path fires ~16x per grid.
                if (s < 18.5f) {
                    // exact XLA-order recompute (validated)
                    float se = 0.0f;
                    for (int ch = 0; ch < NC; ch++) {
                        float d = __fsub_rn(sp[ch * SHW + off], sp[ch * SHW]);
                        se = __fadd_rn(se, __fmul_rn(d, d));
                    }
                    float sd  = fmaxf(__fsqrt_rn(se), EPS_F);
                    float ssq = __fmul_rn(sd, sd);
                    const float* __restrict__ dpp = depth + b * SHW + y * SW + x;
                    float invc = __fdiv_rn(1.0f, __fadd_rn(dpp[0],   1e-6f));
                    float invo = __fdiv_rn(1.0f, __fadd_rn(dpp[off], 1e-6f));
                    float dd   = fmaxf(fabsf(__fsub_rn(invc, invo)), EPS_F);
                    if (dd > EPS_F && sd > EPS_F) {
                        float f1 = xla_expm1_p1(-__fdiv_rn(dd, 10.0f));
                        float f2 = xla_expm1_p1(-ssq);
                        dsum += (double)__fmul_rn(f1, f2);
                    }
                }
            }
        }
    }

    // ---- block reduction -> per-block slot (no hot-path barriers) ----
    const int wid = tid >> 5, lne = tid & 31;
    #pragma unroll
    for (int o = 16; o > 0; o >>= 1)
        dsum += __shfl_down_sync(0xffffffffu, dsum, o);

    __shared__ double ws[8];
    __shared__ bool   is_last;
    if (lne == 0) ws[wid] = dsum;
    __syncthreads();

    const int bid = (blockIdx.z * GYB + blockIdx.y) * GXB + blockIdx.x;
    if (tid == 0) {
        double t = 0.0;
        #pragma unroll
        for (int w = 0; w < 8; w++) t += ws[w];
        g_part[bid] = t;
        __threadfence();
        unsigned old = atomicAdd(&g_ctr, 1u);
        is_last = (old == NBLK - 1);
    }
    __syncthreads();

    // ---- last block finalizes (single launch total) ----
    if (is_last) {
        double v = 0.0;
        for (int i = tid; i < NBLK; i += 256) v += g_part[i];
        #pragma unroll
        for (int o = 16; o > 0; o >>= 1)
            v += __shfl_down_sync(0xffffffffu, v, o);
        __shared__ double fs[8];
        if (lne == 0) fs[wid] = v;
        __syncthreads();
        if (tid == 0) {
            double s = 0.0;
            #pragma unroll
            for (int w = 0; w < 8; w++) s += fs[w];
            // mean over (B,B,k,k,P): S / (25*B*P) = S / 1,767,200
            out[0] = (float)(s / 1767200.0);
            g_ctr  = 0;          // reset for next graph replay
        }
    }
}

extern "C" void kernel_launch(void* const* d_in, const int* in_sizes, int n_in,
                              void* d_out, int out_size) {
    const float* sem   = (const float*)d_in[0];  // (2, 32, 192, 192) f32
    const float* depth = (const float*)d_in[1];  // (2, 1, 192, 192) f32

    dim3 blk(32, 8);
    dim3 grd(GXB, GYB, NB);
    dgp_kernel<<<grd, blk>>>(sem, depth, (float*)d_out);
}